// round 5
// baseline (speedup 1.0000x reference)
#include <cuda_runtime.h>
#include <cuda_bf16.h>
#include <cstdint>

// Fixed problem shapes
#define H_DIM 64
#define W_DIM 176
#define D_DIM 112
#define D4    (D_DIM / 4)          // 28 float4 chunks per feature row
#define CH    (H_DIM - 1)          // 63 cell rows
#define CW    (W_DIM - 1)          // 175 cell cols
#define NCELLS (CH * CW)           // 11025
#define CELLCAP 256                // max points per cell (mean ~45, Poisson)

// Scratch (device globals; no runtime allocation allowed)
__device__ int    g_counts[NCELLS];                  // 44 KB (memset each run)
__device__ float4 g_meta[NCELLS * CELLCAP];          // 45 MB: (wx, wy, idx_bits, valid)

__device__ __forceinline__ void red_add_v4(float* addr, float a, float b, float c, float d) {
    asm volatile("red.global.add.v4.f32 [%0], {%1, %2, %3, %4};"
                 :: "l"(addr), "f"(a), "f"(b), "f"(c), "f"(d)
                 : "memory");
}

// ---------------------------------------------------------------- pass 1: fused bin + weight precompute
__global__ __launch_bounds__(256)
void bin_kernel(const float2* __restrict__ pos,
                const float4* __restrict__ feat,
                float* __restrict__ out,
                int n)
{
    const int i = blockIdx.x * blockDim.x + threadIdx.x;
    if (i >= n) return;

    const float2 p = pos[i];
    const float xf = floorf(p.x);
    const float yf = floorf(p.y);
    const int cx = min(max((int)xf, 0), CW - 1);
    const int cy = min(max((int)yf, 0), CH - 1);
    const float wx = p.x - xf;
    const float wy = p.y - yf;
    const int cell = cy * CW + cx;

    const int slot = atomicAdd(&g_counts[cell], 1);

    if (slot < CELLCAP) {
        g_meta[cell * CELLCAP + slot] = make_float4(wx, wy, __int_as_float(i), 1.0f);
    } else {
        // Overflow fallback (statistically never hit): direct scatter of this point.
        const float w00 = (1.0f - wy) * (1.0f - wx);
        const float w01 = (1.0f - wy) * wx;
        const float w10 = wy * (1.0f - wx);
        const float w11 = wy * wx;
        const float4* frow = feat + (size_t)i * D4;
        float* o00 = out + ((size_t)(cy * W_DIM + cx) * D_DIM);
        float* o01 = o00 + D_DIM;
        float* o10 = o00 + (size_t)W_DIM * D_DIM;
        float* o11 = o10 + D_DIM;
        for (int k = 0; k < D4; k++) {
            const float4 f = frow[k];
            red_add_v4(o00 + k*4, w00*f.x, w00*f.y, w00*f.z, w00*f.w);
            red_add_v4(o01 + k*4, w01*f.x, w01*f.y, w01*f.z, w01*f.w);
            red_add_v4(o10 + k*4, w10*f.x, w10*f.y, w10*f.z, w10*f.w);
            red_add_v4(o11 + k*4, w11*f.x, w11*f.y, w11*f.z, w11*f.w);
        }
    }
}

// ---------------------------------------------------------------- pass 2: CTA-per-cell gather
// Whole cell list staged into smem cooperatively; warp w processes entries
// w, w+4, w+8, ... (perfect intra-CTA balance). Basis accumulators
// s/sx/sy/sxy keep register pressure low; pads (valid=0, wx=wy=0) vanish.
__global__ __launch_bounds__(128, 10)
void cell_kernel(const float4* __restrict__ feat,
                 float* __restrict__ out)
{
    const int cell = blockIdx.x;
    const int warp = threadIdx.x >> 5;
    const int lane = threadIdx.x & 31;
    const int tid  = threadIdx.x;

    const int cnt = min(g_counts[cell], CELLCAP);
    if (cnt == 0) return;
    const int cnt_r = (cnt + 15) & ~15;        // multiple of 16 -> each warp gets a multiple of 4

    __shared__ float4 smeta[CELLCAP];          // 4 KB
    __shared__ float4 sred[4][4][D4];          // 7 KB

    // Cooperative staging: coalesced LDG.128, pads zeroed.
    {
        const float4 z = make_float4(0.f, 0.f, 0.f, 0.f);
        const int base = cell * CELLCAP;
        for (int j = tid; j < cnt_r; j += 128)
            smeta[j] = (j < cnt) ? g_meta[base + j] : z;
    }
    __syncthreads();

    const bool active = (lane < D4);
    float4 s   = {0,0,0,0};   // Σ valid * f
    float4 sx  = {0,0,0,0};   // Σ wx * f
    float4 sy  = {0,0,0,0};   // Σ wy * f
    float4 sxy = {0,0,0,0};   // Σ wx*wy * f

    for (int j = warp; j < cnt_r; j += 16) {
        const float4 m0 = smeta[j];
        const float4 m1 = smeta[j + 4];
        const float4 m2 = smeta[j + 8];
        const float4 m3 = smeta[j + 12];
        const int i0 = __float_as_int(m0.z);
        const int i1 = __float_as_int(m1.z);
        const int i2 = __float_as_int(m2.z);
        const int i3 = __float_as_int(m3.z);
        float4 f0 = {0,0,0,0}, f1 = {0,0,0,0}, f2 = {0,0,0,0}, f3 = {0,0,0,0};
        if (active) {
            f0 = feat[(size_t)i0 * D4 + lane];
            f1 = feat[(size_t)i1 * D4 + lane];
            f2 = feat[(size_t)i2 * D4 + lane];
            f3 = feat[(size_t)i3 * D4 + lane];
        }
        {
            const float pxy = m0.x * m0.y;
            s.x   += m0.w * f0.x; s.y   += m0.w * f0.y; s.z   += m0.w * f0.z; s.w   += m0.w * f0.w;
            sx.x  += m0.x * f0.x; sx.y  += m0.x * f0.y; sx.z  += m0.x * f0.z; sx.w  += m0.x * f0.w;
            sy.x  += m0.y * f0.x; sy.y  += m0.y * f0.y; sy.z  += m0.y * f0.z; sy.w  += m0.y * f0.w;
            sxy.x += pxy  * f0.x; sxy.y += pxy  * f0.y; sxy.z += pxy  * f0.z; sxy.w += pxy  * f0.w;
        }
        {
            const float pxy = m1.x * m1.y;
            s.x   += m1.w * f1.x; s.y   += m1.w * f1.y; s.z   += m1.w * f1.z; s.w   += m1.w * f1.w;
            sx.x  += m1.x * f1.x; sx.y  += m1.x * f1.y; sx.z  += m1.x * f1.z; sx.w  += m1.x * f1.w;
            sy.x  += m1.y * f1.x; sy.y  += m1.y * f1.y; sy.z  += m1.y * f1.z; sy.w  += m1.y * f1.w;
            sxy.x += pxy  * f1.x; sxy.y += pxy  * f1.y; sxy.z += pxy  * f1.z; sxy.w += pxy  * f1.w;
        }
        {
            const float pxy = m2.x * m2.y;
            s.x   += m2.w * f2.x; s.y   += m2.w * f2.y; s.z   += m2.w * f2.z; s.w   += m2.w * f2.w;
            sx.x  += m2.x * f2.x; sx.y  += m2.x * f2.y; sx.z  += m2.x * f2.z; sx.w  += m2.x * f2.w;
            sy.x  += m2.y * f2.x; sy.y  += m2.y * f2.y; sy.z  += m2.y * f2.z; sy.w  += m2.y * f2.w;
            sxy.x += pxy  * f2.x; sxy.y += pxy  * f2.y; sxy.z += pxy  * f2.z; sxy.w += pxy  * f2.w;
        }
        {
            const float pxy = m3.x * m3.y;
            s.x   += m3.w * f3.x; s.y   += m3.w * f3.y; s.z   += m3.w * f3.z; s.w   += m3.w * f3.w;
            sx.x  += m3.x * f3.x; sx.y  += m3.x * f3.y; sx.z  += m3.x * f3.z; sx.w  += m3.x * f3.w;
            sy.x  += m3.y * f3.x; sy.y  += m3.y * f3.y; sy.z  += m3.y * f3.z; sy.w  += m3.y * f3.w;
            sxy.x += pxy  * f3.x; sxy.y += pxy  * f3.y; sxy.z += pxy  * f3.z; sxy.w += pxy  * f3.w;
        }
    }

    // Basis -> corner conversion (per warp, in registers), then cross-warp reduce.
    if (active) {
        float4 a00, a01, a10, a11;
        a11.x = sxy.x;                     a11.y = sxy.y;                     a11.z = sxy.z;                     a11.w = sxy.w;
        a01.x = sx.x - sxy.x;              a01.y = sx.y - sxy.y;              a01.z = sx.z - sxy.z;              a01.w = sx.w - sxy.w;
        a10.x = sy.x - sxy.x;              a10.y = sy.y - sxy.y;              a10.z = sy.z - sxy.z;              a10.w = sy.w - sxy.w;
        a00.x = s.x - sx.x - sy.x + sxy.x; a00.y = s.y - sx.y - sy.y + sxy.y;
        a00.z = s.z - sx.z - sy.z + sxy.z; a00.w = s.w - sx.w - sy.w + sxy.w;
        sred[warp][0][lane] = a00;
        sred[warp][1][lane] = a01;
        sred[warp][2][lane] = a10;
        sred[warp][3][lane] = a11;
    }
    __syncthreads();

    // 112 threads: thread t -> corner t/28, chunk t%28. One RED.v4 each.
    if (tid < 4 * D4) {
        const int c = tid / D4;
        const int k = tid - c * D4;
        const float4 v0 = sred[0][c][k], v1 = sred[1][c][k];
        const float4 v2 = sred[2][c][k], v3 = sred[3][c][k];
        const float vx = v0.x + v1.x + v2.x + v3.x;
        const float vy = v0.y + v1.y + v2.y + v3.y;
        const float vz = v0.z + v1.z + v2.z + v3.z;
        const float vw = v0.w + v1.w + v2.w + v3.w;
        const int cy = cell / CW;
        const int cx = cell - cy * CW;
        const int dy = c >> 1, dx = c & 1;
        float* addr = out + ((size_t)((cy + dy) * W_DIM + (cx + dx)) * D_DIM + k * 4);
        red_add_v4(addr, vx, vy, vz, vw);
    }
}

// ---------------------------------------------------------------- launch
extern "C" void kernel_launch(void* const* d_in, const int* in_sizes, int n_in,
                              void* d_out, int out_size)
{
    const float2* pos  = (const float2*)d_in[0];
    const float4* feat = (const float4*)d_in[1];
    float* out = (float*)d_out;
    const int n = in_sizes[0] / 2;

    void* counts_ptr = nullptr;
    cudaGetSymbolAddress(&counts_ptr, g_counts);

    cudaMemsetAsync(out, 0, (size_t)out_size * sizeof(float));
    cudaMemsetAsync(counts_ptr, 0, sizeof(int) * NCELLS);

    bin_kernel<<<(n + 255) / 256, 256>>>(pos, feat, out, n);
    cell_kernel<<<NCELLS, 128>>>(feat, out);
}

// round 6
// speedup vs baseline: 1.0873x; 1.0873x over previous
#include <cuda_runtime.h>
#include <cuda_bf16.h>
#include <cstdint>

// Fixed problem shapes
#define H_DIM 64
#define W_DIM 176
#define D_DIM 112
#define D4    (D_DIM / 4)          // 28 float4 chunks per feature row
#define CH    (H_DIM - 1)          // 63 cell rows
#define CW    (W_DIM - 1)          // 175 cell cols
#define NCELLS (CH * CW)           // 11025
#define NSUB   4                   // sub-lists per cell == warps per CTA
#define SUBCAP 64                  // slots per sub-list
#define CELLCAP (NSUB * SUBCAP)

#define INV65535 (1.0f / 65535.0f)

// Scratch (device globals; no runtime allocation allowed)
__device__ int  g_counts[NCELLS * NSUB];            // 176 KB (memset each run)
__device__ int2 g_meta[NCELLS * CELLCAP];           // 22.6 MB: (idx | -1, qy<<16|qx)

__device__ __forceinline__ void red_add_v4(float* addr, float a, float b, float c, float d) {
    asm volatile("red.global.add.v4.f32 [%0], {%1, %2, %3, %4};"
                 :: "l"(addr), "f"(a), "f"(b), "f"(c), "f"(d)
                 : "memory");
}

// ---------------------------------------------------------------- pass 1: fused bin + weight precompute
__global__ __launch_bounds__(256)
void bin_kernel(const float2* __restrict__ pos,
                const float4* __restrict__ feat,
                float* __restrict__ out,
                int n)
{
    const int i = blockIdx.x * blockDim.x + threadIdx.x;
    if (i >= n) return;

    const float2 p = pos[i];
    const float xf = floorf(p.x);
    const float yf = floorf(p.y);
    const int cx = min(max((int)xf, 0), CW - 1);
    const int cy = min(max((int)yf, 0), CH - 1);
    const float wx = p.x - xf;
    const float wy = p.y - yf;
    const int cell = cy * CW + cx;

    const int sub  = i & (NSUB - 1);
    const int slot = atomicAdd(&g_counts[cell * NSUB + sub], 1);

    if (slot < SUBCAP) {
        const unsigned qx = (unsigned)__float2int_rn(wx * 65535.0f);
        const unsigned qy = (unsigned)__float2int_rn(wy * 65535.0f);
        g_meta[(cell * NSUB + sub) * SUBCAP + slot] = make_int2(i, (int)((qy << 16) | qx));
    } else {
        // Overflow fallback (statistically never hit): direct scatter of this point.
        const float w00 = (1.0f - wy) * (1.0f - wx);
        const float w01 = (1.0f - wy) * wx;
        const float w10 = wy * (1.0f - wx);
        const float w11 = wy * wx;
        const float4* frow = feat + (size_t)i * D4;
        float* o00 = out + ((size_t)(cy * W_DIM + cx) * D_DIM);
        float* o01 = o00 + D_DIM;
        float* o10 = o00 + (size_t)W_DIM * D_DIM;
        float* o11 = o10 + D_DIM;
        for (int k = 0; k < D4; k++) {
            const float4 f = frow[k];
            red_add_v4(o00 + k*4, w00*f.x, w00*f.y, w00*f.z, w00*f.w);
            red_add_v4(o01 + k*4, w01*f.x, w01*f.y, w01*f.z, w01*f.w);
            red_add_v4(o10 + k*4, w10*f.x, w10*f.y, w10*f.z, w10*f.w);
            red_add_v4(o11 + k*4, w11*f.x, w11*f.y, w11*f.z, w11*f.w);
        }
    }
}

// Unpack one meta entry -> (idx, u=(1-wx)*valid, v=wx*valid, wy)
__device__ __forceinline__ void unpack_meta(int2 m, int& idx, float& u, float& v, float& wy) {
    const float valid = (m.x >= 0) ? 1.0f : 0.0f;
    idx = max(m.x, 0);
    const float wx = (float)((unsigned)m.y & 0xFFFFu) * INV65535;
    wy = (float)((unsigned)m.y >> 16) * INV65535;
    u = (1.0f - wx) * valid;
    v = wx * valid;
}

// ---------------------------------------------------------------- pass 2: CTA-per-cell gather
// Warp w consumes sub-list w (R4 structure). 4-deep feature-load batching
// preserves MLP=4; pads carry idx=-1 -> zero weights.
__global__ __launch_bounds__(128, 8)
void cell_kernel(const float4* __restrict__ feat,
                 float* __restrict__ out)
{
    const int cell = blockIdx.x;
    const int warp = threadIdx.x >> 5;
    const int lane = threadIdx.x & 31;

    // All 4 sub-counts with one int4 load (warp-uniform)
    const int4 c4 = *reinterpret_cast<const int4*>(&g_counts[cell * NSUB]);
    const int total = min(c4.x, SUBCAP) + min(c4.y, SUBCAP)
                    + min(c4.z, SUBCAP) + min(c4.w, SUBCAP);
    if (total == 0) return;

    const int cnt = min(warp == 0 ? c4.x : warp == 1 ? c4.y : warp == 2 ? c4.z : c4.w, SUBCAP);
    const int cnt_r = (cnt + 3) & ~3;          // rounded up; pads are idx=-1

    __shared__ int2   smeta[NSUB][SUBCAP];     // 2 KB
    __shared__ float4 sred[NSUB][4][D4];       // 7 KB

    // Stage sub-list metadata: 2 coalesced LDG.64 per warp, pad with {-1,0}.
    {
        const int2 z = make_int2(-1, 0);
        const int base = (cell * NSUB + warp) * SUBCAP;
        smeta[warp][lane]      = (lane      < cnt) ? g_meta[base + lane]      : z;
        smeta[warp][lane + 32] = (lane + 32 < cnt) ? g_meta[base + lane + 32] : z;
    }
    __syncwarp();

    const bool active = (lane < D4);
    float4 a00 = {0,0,0,0}, a01 = {0,0,0,0}, a10 = {0,0,0,0}, a11 = {0,0,0,0};

    for (int i = 0; i < cnt_r; i += 4) {
        int i0, i1, i2, i3;
        float u0, v0, wy0, u1, v1, wy1, u2, v2, wy2, u3, v3, wy3;
        unpack_meta(smeta[warp][i + 0], i0, u0, v0, wy0);
        unpack_meta(smeta[warp][i + 1], i1, u1, v1, wy1);
        unpack_meta(smeta[warp][i + 2], i2, u2, v2, wy2);
        unpack_meta(smeta[warp][i + 3], i3, u3, v3, wy3);

        float4 f0 = {0,0,0,0}, f1 = {0,0,0,0}, f2 = {0,0,0,0}, f3 = {0,0,0,0};
        if (active) {
            f0 = feat[(size_t)i0 * D4 + lane];
            f1 = feat[(size_t)i1 * D4 + lane];
            f2 = feat[(size_t)i2 * D4 + lane];
            f3 = feat[(size_t)i3 * D4 + lane];
        }
        {
            const float w00 = (1.0f - wy0) * u0, w01 = (1.0f - wy0) * v0;
            const float w10 = wy0 * u0,          w11 = wy0 * v0;
            a00.x += w00*f0.x; a00.y += w00*f0.y; a00.z += w00*f0.z; a00.w += w00*f0.w;
            a01.x += w01*f0.x; a01.y += w01*f0.y; a01.z += w01*f0.z; a01.w += w01*f0.w;
            a10.x += w10*f0.x; a10.y += w10*f0.y; a10.z += w10*f0.z; a10.w += w10*f0.w;
            a11.x += w11*f0.x; a11.y += w11*f0.y; a11.z += w11*f0.z; a11.w += w11*f0.w;
        }
        {
            const float w00 = (1.0f - wy1) * u1, w01 = (1.0f - wy1) * v1;
            const float w10 = wy1 * u1,          w11 = wy1 * v1;
            a00.x += w00*f1.x; a00.y += w00*f1.y; a00.z += w00*f1.z; a00.w += w00*f1.w;
            a01.x += w01*f1.x; a01.y += w01*f1.y; a01.z += w01*f1.z; a01.w += w01*f1.w;
            a10.x += w10*f1.x; a10.y += w10*f1.y; a10.z += w10*f1.z; a10.w += w10*f1.w;
            a11.x += w11*f1.x; a11.y += w11*f1.y; a11.z += w11*f1.z; a11.w += w11*f1.w;
        }
        {
            const float w00 = (1.0f - wy2) * u2, w01 = (1.0f - wy2) * v2;
            const float w10 = wy2 * u2,          w11 = wy2 * v2;
            a00.x += w00*f2.x; a00.y += w00*f2.y; a00.z += w00*f2.z; a00.w += w00*f2.w;
            a01.x += w01*f2.x; a01.y += w01*f2.y; a01.z += w01*f2.z; a01.w += w01*f2.w;
            a10.x += w10*f2.x; a10.y += w10*f2.y; a10.z += w10*f2.z; a10.w += w10*f2.w;
            a11.x += w11*f2.x; a11.y += w11*f2.y; a11.z += w11*f2.z; a11.w += w11*f2.w;
        }
        {
            const float w00 = (1.0f - wy3) * u3, w01 = (1.0f - wy3) * v3;
            const float w10 = wy3 * u3,          w11 = wy3 * v3;
            a00.x += w00*f3.x; a00.y += w00*f3.y; a00.z += w00*f3.z; a00.w += w00*f3.w;
            a01.x += w01*f3.x; a01.y += w01*f3.y; a01.z += w01*f3.z; a01.w += w01*f3.w;
            a10.x += w10*f3.x; a10.y += w10*f3.y; a10.z += w10*f3.z; a10.w += w10*f3.w;
            a11.x += w11*f3.x; a11.y += w11*f3.y; a11.z += w11*f3.z; a11.w += w11*f3.w;
        }
    }

    // Cross-warp reduce through smem
    if (active) {
        sred[warp][0][lane] = a00;
        sred[warp][1][lane] = a01;
        sred[warp][2][lane] = a10;
        sred[warp][3][lane] = a11;
    }
    __syncthreads();

    // 112 threads: thread t -> corner t/28, chunk t%28. One RED.v4 each.
    const int t = threadIdx.x;
    if (t < 4 * D4) {
        const int c = t / D4;
        const int k = t - c * D4;
        const float4 v0 = sred[0][c][k], v1 = sred[1][c][k];
        const float4 v2 = sred[2][c][k], v3 = sred[3][c][k];
        const float vx = v0.x + v1.x + v2.x + v3.x;
        const float vy = v0.y + v1.y + v2.y + v3.y;
        const float vz = v0.z + v1.z + v2.z + v3.z;
        const float vw = v0.w + v1.w + v2.w + v3.w;
        const int cy = cell / CW;
        const int cx = cell - cy * CW;
        const int dy = c >> 1, dx = c & 1;
        float* addr = out + ((size_t)((cy + dy) * W_DIM + (cx + dx)) * D_DIM + k * 4);
        red_add_v4(addr, vx, vy, vz, vw);
    }
}

// ---------------------------------------------------------------- launch
extern "C" void kernel_launch(void* const* d_in, const int* in_sizes, int n_in,
                              void* d_out, int out_size)
{
    const float2* pos  = (const float2*)d_in[0];
    const float4* feat = (const float4*)d_in[1];
    float* out = (float*)d_out;
    const int n = in_sizes[0] / 2;

    void* counts_ptr = nullptr;
    cudaGetSymbolAddress(&counts_ptr, g_counts);

    cudaMemsetAsync(out, 0, (size_t)out_size * sizeof(float));
    cudaMemsetAsync(counts_ptr, 0, sizeof(int) * NCELLS * NSUB);

    bin_kernel<<<(n + 255) / 256, 256>>>(pos, feat, out, n);
    cell_kernel<<<NCELLS, 128>>>(feat, out);
}

// round 7
// speedup vs baseline: 1.1194x; 1.0295x over previous
#include <cuda_runtime.h>
#include <cuda_bf16.h>
#include <cstdint>

// Fixed problem shapes
#define H_DIM 64
#define W_DIM 176
#define D_DIM 112
#define D4    (D_DIM / 4)          // 28 float4 chunks per feature row
#define CH    (H_DIM - 1)          // 63 cell rows
#define CW    (W_DIM - 1)          // 175 cell cols
#define NCELLS (CH * CW)           // 11025
#define CELLCAP 256                // max points per cell (mean ~45, Poisson)

// Scratch (device globals; no runtime allocation allowed)
__device__ int    g_counts[NCELLS];                  // 44 KB (memset each run)
__device__ float4 g_meta[NCELLS * CELLCAP];          // 45 MB: (wx, wy, idx_bits, valid)

__device__ __forceinline__ void red_add_v4(float* addr, float a, float b, float c, float d) {
    asm volatile("red.global.add.v4.f32 [%0], {%1, %2, %3, %4};"
                 :: "l"(addr), "f"(a), "f"(b), "f"(c), "f"(d)
                 : "memory");
}

// ---------------------------------------------------------------- pass 1: fused bin + weight precompute
__global__ __launch_bounds__(256)
void bin_kernel(const float2* __restrict__ pos,
                const float4* __restrict__ feat,
                float* __restrict__ out,
                int n)
{
    const int i = blockIdx.x * blockDim.x + threadIdx.x;
    if (i >= n) return;

    const float2 p = pos[i];
    const float xf = floorf(p.x);
    const float yf = floorf(p.y);
    const int cx = min(max((int)xf, 0), CW - 1);
    const int cy = min(max((int)yf, 0), CH - 1);
    const float wx = p.x - xf;
    const float wy = p.y - yf;
    const int cell = cy * CW + cx;

    const int slot = atomicAdd(&g_counts[cell], 1);

    if (slot < CELLCAP) {
        g_meta[cell * CELLCAP + slot] = make_float4(wx, wy, __int_as_float(i), 1.0f);
    } else {
        // Overflow fallback (statistically never hit): direct scatter of this point.
        const float w00 = (1.0f - wy) * (1.0f - wx);
        const float w01 = (1.0f - wy) * wx;
        const float w10 = wy * (1.0f - wx);
        const float w11 = wy * wx;
        const float4* frow = feat + (size_t)i * D4;
        float* o00 = out + ((size_t)(cy * W_DIM + cx) * D_DIM);
        float* o01 = o00 + D_DIM;
        float* o10 = o00 + (size_t)W_DIM * D_DIM;
        float* o11 = o10 + D_DIM;
        for (int k = 0; k < D4; k++) {
            const float4 f = frow[k];
            red_add_v4(o00 + k*4, w00*f.x, w00*f.y, w00*f.z, w00*f.w);
            red_add_v4(o01 + k*4, w01*f.x, w01*f.y, w01*f.z, w01*f.w);
            red_add_v4(o10 + k*4, w10*f.x, w10*f.y, w10*f.z, w10*f.w);
            red_add_v4(o11 + k*4, w11*f.x, w11*f.y, w11*f.z, w11*f.w);
        }
    }
}

// ---------------------------------------------------------------- pass 2: CTA-per-cell gather
// Pooled cell list in smem; warp w processes entries w, w+4, w+8, ...
// (balanced to +/-4 points). __launch_bounds__(128, 8) leaves ptxas the full
// 64-reg budget so all 4 feature float4s stay live (MLP=4, the R4 regime).
// Basis accumulators s/sx/sy/sxy: pads (valid=0, wx=wy=0) vanish.
__global__ __launch_bounds__(128, 8)
void cell_kernel(const float4* __restrict__ feat,
                 float* __restrict__ out)
{
    const int cell = blockIdx.x;
    const int warp = threadIdx.x >> 5;
    const int lane = threadIdx.x & 31;
    const int tid  = threadIdx.x;

    const int cnt = min(g_counts[cell], CELLCAP);
    if (cnt == 0) return;
    const int cnt_r = (cnt + 15) & ~15;        // multiple of 16 -> each warp runs equal iters

    __shared__ float4 smeta[CELLCAP];          // 4 KB
    __shared__ float4 sred[4][4][D4];          // 7 KB

    // Cooperative staging: coalesced LDG.128, pads zeroed.
    {
        const float4 z = make_float4(0.f, 0.f, 0.f, 0.f);
        const int base = cell * CELLCAP;
        for (int j = tid; j < cnt_r; j += 128)
            smeta[j] = (j < cnt) ? g_meta[base + j] : z;
    }
    __syncthreads();

    const bool active = (lane < D4);
    float4 s   = {0,0,0,0};   // Σ valid * f
    float4 sx  = {0,0,0,0};   // Σ wx * f
    float4 sy  = {0,0,0,0};   // Σ wy * f
    float4 sxy = {0,0,0,0};   // Σ wx*wy * f

    for (int j = warp; j < cnt_r; j += 16) {
        const float4 m0 = smeta[j];
        const float4 m1 = smeta[j + 4];
        const float4 m2 = smeta[j + 8];
        const float4 m3 = smeta[j + 12];
        const int i0 = __float_as_int(m0.z);
        const int i1 = __float_as_int(m1.z);
        const int i2 = __float_as_int(m2.z);
        const int i3 = __float_as_int(m3.z);
        float4 f0 = {0,0,0,0}, f1 = {0,0,0,0}, f2 = {0,0,0,0}, f3 = {0,0,0,0};
        if (active) {
            f0 = feat[(size_t)i0 * D4 + lane];
            f1 = feat[(size_t)i1 * D4 + lane];
            f2 = feat[(size_t)i2 * D4 + lane];
            f3 = feat[(size_t)i3 * D4 + lane];
        }
        {
            const float pxy = m0.x * m0.y;
            s.x   += m0.w * f0.x; s.y   += m0.w * f0.y; s.z   += m0.w * f0.z; s.w   += m0.w * f0.w;
            sx.x  += m0.x * f0.x; sx.y  += m0.x * f0.y; sx.z  += m0.x * f0.z; sx.w  += m0.x * f0.w;
            sy.x  += m0.y * f0.x; sy.y  += m0.y * f0.y; sy.z  += m0.y * f0.z; sy.w  += m0.y * f0.w;
            sxy.x += pxy  * f0.x; sxy.y += pxy  * f0.y; sxy.z += pxy  * f0.z; sxy.w += pxy  * f0.w;
        }
        {
            const float pxy = m1.x * m1.y;
            s.x   += m1.w * f1.x; s.y   += m1.w * f1.y; s.z   += m1.w * f1.z; s.w   += m1.w * f1.w;
            sx.x  += m1.x * f1.x; sx.y  += m1.x * f1.y; sx.z  += m1.x * f1.z; sx.w  += m1.x * f1.w;
            sy.x  += m1.y * f1.x; sy.y  += m1.y * f1.y; sy.z  += m1.y * f1.z; sy.w  += m1.y * f1.w;
            sxy.x += pxy  * f1.x; sxy.y += pxy  * f1.y; sxy.z += pxy  * f1.z; sxy.w += pxy  * f1.w;
        }
        {
            const float pxy = m2.x * m2.y;
            s.x   += m2.w * f2.x; s.y   += m2.w * f2.y; s.z   += m2.w * f2.z; s.w   += m2.w * f2.w;
            sx.x  += m2.x * f2.x; sx.y  += m2.x * f2.y; sx.z  += m2.x * f2.z; sx.w  += m2.x * f2.w;
            sy.x  += m2.y * f2.x; sy.y  += m2.y * f2.y; sy.z  += m2.y * f2.z; sy.w  += m2.y * f2.w;
            sxy.x += pxy  * f2.x; sxy.y += pxy  * f2.y; sxy.z += pxy  * f2.z; sxy.w += pxy  * f2.w;
        }
        {
            const float pxy = m3.x * m3.y;
            s.x   += m3.w * f3.x; s.y   += m3.w * f3.y; s.z   += m3.w * f3.z; s.w   += m3.w * f3.w;
            sx.x  += m3.x * f3.x; sx.y  += m3.x * f3.y; sx.z  += m3.x * f3.z; sx.w  += m3.x * f3.w;
            sy.x  += m3.y * f3.x; sy.y  += m3.y * f3.y; sy.z  += m3.y * f3.z; sy.w  += m3.y * f3.w;
            sxy.x += pxy  * f3.x; sxy.y += pxy  * f3.y; sxy.z += pxy  * f3.z; sxy.w += pxy  * f3.w;
        }
    }

    // Basis -> corner conversion (per warp, in registers), then cross-warp reduce.
    if (active) {
        float4 a00, a01, a10, a11;
        a11.x = sxy.x;                     a11.y = sxy.y;                     a11.z = sxy.z;                     a11.w = sxy.w;
        a01.x = sx.x - sxy.x;              a01.y = sx.y - sxy.y;              a01.z = sx.z - sxy.z;              a01.w = sx.w - sxy.w;
        a10.x = sy.x - sxy.x;              a10.y = sy.y - sxy.y;              a10.z = sy.z - sxy.z;              a10.w = sy.w - sxy.w;
        a00.x = s.x - sx.x - sy.x + sxy.x; a00.y = s.y - sx.y - sy.y + sxy.y;
        a00.z = s.z - sx.z - sy.z + sxy.z; a00.w = s.w - sx.w - sy.w + sxy.w;
        sred[warp][0][lane] = a00;
        sred[warp][1][lane] = a01;
        sred[warp][2][lane] = a10;
        sred[warp][3][lane] = a11;
    }
    __syncthreads();

    // 112 threads: thread t -> corner t/28, chunk t%28. One RED.v4 each.
    if (tid < 4 * D4) {
        const int c = tid / D4;
        const int k = tid - c * D4;
        const float4 v0 = sred[0][c][k], v1 = sred[1][c][k];
        const float4 v2 = sred[2][c][k], v3 = sred[3][c][k];
        const float vx = v0.x + v1.x + v2.x + v3.x;
        const float vy = v0.y + v1.y + v2.y + v3.y;
        const float vz = v0.z + v1.z + v2.z + v3.z;
        const float vw = v0.w + v1.w + v2.w + v3.w;
        const int cy = cell / CW;
        const int cx = cell - cy * CW;
        const int dy = c >> 1, dx = c & 1;
        float* addr = out + ((size_t)((cy + dy) * W_DIM + (cx + dx)) * D_DIM + k * 4);
        red_add_v4(addr, vx, vy, vz, vw);
    }
}

// ---------------------------------------------------------------- launch
extern "C" void kernel_launch(void* const* d_in, const int* in_sizes, int n_in,
                              void* d_out, int out_size)
{
    const float2* pos  = (const float2*)d_in[0];
    const float4* feat = (const float4*)d_in[1];
    float* out = (float*)d_out;
    const int n = in_sizes[0] / 2;

    void* counts_ptr = nullptr;
    cudaGetSymbolAddress(&counts_ptr, g_counts);

    cudaMemsetAsync(out, 0, (size_t)out_size * sizeof(float));
    cudaMemsetAsync(counts_ptr, 0, sizeof(int) * NCELLS);

    bin_kernel<<<(n + 255) / 256, 256>>>(pos, feat, out, n);
    cell_kernel<<<NCELLS, 128>>>(feat, out);
}

// round 8
// speedup vs baseline: 1.1236x; 1.0038x over previous
#include <cuda_runtime.h>
#include <cuda_bf16.h>
#include <cstdint>

// Fixed problem shapes
#define H_DIM 64
#define W_DIM 176
#define D_DIM 112
#define D4    (D_DIM / 4)          // 28 float4 chunks per feature row
#define CH    (H_DIM - 1)          // 63 cell rows
#define CW    (W_DIM - 1)          // 175 cell cols
#define NCELLS (CH * CW)           // 11025
#define CELLCAP 256                // max points per cell (mean ~45, Poisson)

// Scratch (device globals; no runtime allocation allowed)
__device__ int    g_counts[NCELLS];                  // 44 KB (memset each run)
__device__ float4 g_meta[NCELLS * CELLCAP];          // 45 MB: (wx, wy, idx_bits, valid)

__device__ __forceinline__ void red_add_v4(float* addr, float a, float b, float c, float d) {
    asm volatile("red.global.add.v4.f32 [%0], {%1, %2, %3, %4};"
                 :: "l"(addr), "f"(a), "f"(b), "f"(c), "f"(d)
                 : "memory");
}

// Packed f32x2 FMA (Blackwell): d = a * b + c on two lanes of a 64-bit pair.
__device__ __forceinline__ void fma_f32x2(unsigned long long& d,
                                          unsigned long long a,
                                          unsigned long long b,
                                          unsigned long long c) {
    asm("fma.rn.f32x2 %0, %1, %2, %3;" : "=l"(d) : "l"(a), "l"(b), "l"(c));
}

// Broadcast one float into both halves of an f32x2 pair.
__device__ __forceinline__ unsigned long long bcast_f32x2(float w) {
    unsigned long long r;
    asm("mov.b64 %0, {%1, %1};" : "=l"(r) : "f"(w));
    return r;
}

__device__ __forceinline__ float2 unpack_f32x2(unsigned long long v) {
    float lo, hi;
    asm("mov.b64 {%0, %1}, %2;" : "=f"(lo), "=f"(hi) : "l"(v));
    return make_float2(lo, hi);
}

// ---------------------------------------------------------------- pass 1: fused bin + weight precompute
__global__ __launch_bounds__(256)
void bin_kernel(const float2* __restrict__ pos,
                const float4* __restrict__ feat,
                float* __restrict__ out,
                int n)
{
    const int i = blockIdx.x * blockDim.x + threadIdx.x;
    if (i >= n) return;

    const float2 p = pos[i];
    const float xf = floorf(p.x);
    const float yf = floorf(p.y);
    const int cx = min(max((int)xf, 0), CW - 1);
    const int cy = min(max((int)yf, 0), CH - 1);
    const float wx = p.x - xf;
    const float wy = p.y - yf;
    const int cell = cy * CW + cx;

    const int slot = atomicAdd(&g_counts[cell], 1);

    if (slot < CELLCAP) {
        g_meta[cell * CELLCAP + slot] = make_float4(wx, wy, __int_as_float(i), 1.0f);
    } else {
        // Overflow fallback (statistically never hit): direct scatter of this point.
        const float w00 = (1.0f - wy) * (1.0f - wx);
        const float w01 = (1.0f - wy) * wx;
        const float w10 = wy * (1.0f - wx);
        const float w11 = wy * wx;
        const float4* frow = feat + (size_t)i * D4;
        float* o00 = out + ((size_t)(cy * W_DIM + cx) * D_DIM);
        float* o01 = o00 + D_DIM;
        float* o10 = o00 + (size_t)W_DIM * D_DIM;
        float* o11 = o10 + D_DIM;
        for (int k = 0; k < D4; k++) {
            const float4 f = frow[k];
            red_add_v4(o00 + k*4, w00*f.x, w00*f.y, w00*f.z, w00*f.w);
            red_add_v4(o01 + k*4, w01*f.x, w01*f.y, w01*f.z, w01*f.w);
            red_add_v4(o10 + k*4, w10*f.x, w10*f.y, w10*f.z, w10*f.w);
            red_add_v4(o11 + k*4, w11*f.x, w11*f.y, w11*f.z, w11*f.w);
        }
    }
}

// ---------------------------------------------------------------- pass 2: CTA-per-cell gather
// R7 structure (pooled list, stride-16 warp split, MLP=4) with:
//  - packed fma.rn.f32x2 accumulation (8 FFMA2/pt/lane instead of 16 FFMA)
//  - 32-bit feature indexing (feat elements < 2^31)
__global__ __launch_bounds__(128, 8)
void cell_kernel(const float4* __restrict__ feat,
                 float* __restrict__ out)
{
    const int cell = blockIdx.x;
    const int warp = threadIdx.x >> 5;
    const int lane = threadIdx.x & 31;
    const int tid  = threadIdx.x;

    const int cnt = min(g_counts[cell], CELLCAP);
    if (cnt == 0) return;
    const int cnt_r = (cnt + 15) & ~15;        // multiple of 16 -> equal iters per warp

    __shared__ float4 smeta[CELLCAP];          // 4 KB
    __shared__ float4 sred[4][4][D4];          // 7 KB

    // Cooperative staging: coalesced LDG.128, pads zeroed (-> weights 0).
    {
        const float4 z = make_float4(0.f, 0.f, 0.f, 0.f);
        const int base = cell * CELLCAP;
        for (int j = tid; j < cnt_r; j += 128)
            smeta[j] = (j < cnt) ? g_meta[base + j] : z;
    }
    __syncthreads();

    const bool active = (lane < D4);
    const ulonglong2* featp = reinterpret_cast<const ulonglong2*>(feat);

    // Packed accumulators: {lo = comps 0,1; hi = comps 2,3} per basis sum.
    unsigned long long s_lo = 0,  s_hi = 0;    // Σ valid * f
    unsigned long long sx_lo = 0, sx_hi = 0;   // Σ wx * f
    unsigned long long sy_lo = 0, sy_hi = 0;   // Σ wy * f
    unsigned long long sp_lo = 0, sp_hi = 0;   // Σ wx*wy * f

    for (int j = warp; j < cnt_r; j += 16) {
        const float4 m0 = smeta[j];
        const float4 m1 = smeta[j + 4];
        const float4 m2 = smeta[j + 8];
        const float4 m3 = smeta[j + 12];
        // 32-bit offsets (feat has 500000*28 = 14M float4 < 2^31)
        const int o0 = __float_as_int(m0.z) * D4 + lane;
        const int o1 = __float_as_int(m1.z) * D4 + lane;
        const int o2 = __float_as_int(m2.z) * D4 + lane;
        const int o3 = __float_as_int(m3.z) * D4 + lane;

        ulonglong2 f0 = {0,0}, f1 = {0,0}, f2 = {0,0}, f3 = {0,0};
        if (active) {
            f0 = featp[o0];
            f1 = featp[o1];
            f2 = featp[o2];
            f3 = featp[o3];
        }
        {
            const unsigned long long wv = bcast_f32x2(m0.w);
            const unsigned long long wx = bcast_f32x2(m0.x);
            const unsigned long long wy = bcast_f32x2(m0.y);
            const unsigned long long wp = bcast_f32x2(m0.x * m0.y);
            fma_f32x2(s_lo,  wv, f0.x, s_lo);   fma_f32x2(s_hi,  wv, f0.y, s_hi);
            fma_f32x2(sx_lo, wx, f0.x, sx_lo);  fma_f32x2(sx_hi, wx, f0.y, sx_hi);
            fma_f32x2(sy_lo, wy, f0.x, sy_lo);  fma_f32x2(sy_hi, wy, f0.y, sy_hi);
            fma_f32x2(sp_lo, wp, f0.x, sp_lo);  fma_f32x2(sp_hi, wp, f0.y, sp_hi);
        }
        {
            const unsigned long long wv = bcast_f32x2(m1.w);
            const unsigned long long wx = bcast_f32x2(m1.x);
            const unsigned long long wy = bcast_f32x2(m1.y);
            const unsigned long long wp = bcast_f32x2(m1.x * m1.y);
            fma_f32x2(s_lo,  wv, f1.x, s_lo);   fma_f32x2(s_hi,  wv, f1.y, s_hi);
            fma_f32x2(sx_lo, wx, f1.x, sx_lo);  fma_f32x2(sx_hi, wx, f1.y, sx_hi);
            fma_f32x2(sy_lo, wy, f1.x, sy_lo);  fma_f32x2(sy_hi, wy, f1.y, sy_hi);
            fma_f32x2(sp_lo, wp, f1.x, sp_lo);  fma_f32x2(sp_hi, wp, f1.y, sp_hi);
        }
        {
            const unsigned long long wv = bcast_f32x2(m2.w);
            const unsigned long long wx = bcast_f32x2(m2.x);
            const unsigned long long wy = bcast_f32x2(m2.y);
            const unsigned long long wp = bcast_f32x2(m2.x * m2.y);
            fma_f32x2(s_lo,  wv, f2.x, s_lo);   fma_f32x2(s_hi,  wv, f2.y, s_hi);
            fma_f32x2(sx_lo, wx, f2.x, sx_lo);  fma_f32x2(sx_hi, wx, f2.y, sx_hi);
            fma_f32x2(sy_lo, wy, f2.x, sy_lo);  fma_f32x2(sy_hi, wy, f2.y, sy_hi);
            fma_f32x2(sp_lo, wp, f2.x, sp_lo);  fma_f32x2(sp_hi, wp, f2.y, sp_hi);
        }
        {
            const unsigned long long wv = bcast_f32x2(m3.w);
            const unsigned long long wx = bcast_f32x2(m3.x);
            const unsigned long long wy = bcast_f32x2(m3.y);
            const unsigned long long wp = bcast_f32x2(m3.x * m3.y);
            fma_f32x2(s_lo,  wv, f3.x, s_lo);   fma_f32x2(s_hi,  wv, f3.y, s_hi);
            fma_f32x2(sx_lo, wx, f3.x, sx_lo);  fma_f32x2(sx_hi, wx, f3.y, sx_hi);
            fma_f32x2(sy_lo, wy, f3.x, sy_lo);  fma_f32x2(sy_hi, wy, f3.y, sy_hi);
            fma_f32x2(sp_lo, wp, f3.x, sp_lo);  fma_f32x2(sp_hi, wp, f3.y, sp_hi);
        }
    }

    // Unpack, basis -> corner conversion, cross-warp reduce.
    if (active) {
        const float2 s01  = unpack_f32x2(s_lo),  s23  = unpack_f32x2(s_hi);
        const float2 sx01 = unpack_f32x2(sx_lo), sx23 = unpack_f32x2(sx_hi);
        const float2 sy01 = unpack_f32x2(sy_lo), sy23 = unpack_f32x2(sy_hi);
        const float2 sp01 = unpack_f32x2(sp_lo), sp23 = unpack_f32x2(sp_hi);

        float4 a00, a01, a10, a11;
        a11 = make_float4(sp01.x, sp01.y, sp23.x, sp23.y);
        a01 = make_float4(sx01.x - sp01.x, sx01.y - sp01.y, sx23.x - sp23.x, sx23.y - sp23.y);
        a10 = make_float4(sy01.x - sp01.x, sy01.y - sp01.y, sy23.x - sp23.x, sy23.y - sp23.y);
        a00 = make_float4(s01.x - sx01.x - sy01.x + sp01.x,
                          s01.y - sx01.y - sy01.y + sp01.y,
                          s23.x - sx23.x - sy23.x + sp23.x,
                          s23.y - sx23.y - sy23.y + sp23.y);
        sred[warp][0][lane] = a00;
        sred[warp][1][lane] = a01;
        sred[warp][2][lane] = a10;
        sred[warp][3][lane] = a11;
    }
    __syncthreads();

    // 112 threads: thread t -> corner t/28, chunk t%28. One RED.v4 each.
    if (tid < 4 * D4) {
        const int c = tid / D4;
        const int k = tid - c * D4;
        const float4 v0 = sred[0][c][k], v1 = sred[1][c][k];
        const float4 v2 = sred[2][c][k], v3 = sred[3][c][k];
        const float vx = v0.x + v1.x + v2.x + v3.x;
        const float vy = v0.y + v1.y + v2.y + v3.y;
        const float vz = v0.z + v1.z + v2.z + v3.z;
        const float vw = v0.w + v1.w + v2.w + v3.w;
        const int cy = cell / CW;
        const int cx = cell - cy * CW;
        const int dy = c >> 1, dx = c & 1;
        float* addr = out + ((size_t)((cy + dy) * W_DIM + (cx + dx)) * D_DIM + k * 4);
        red_add_v4(addr, vx, vy, vz, vw);
    }
}

// ---------------------------------------------------------------- launch
extern "C" void kernel_launch(void* const* d_in, const int* in_sizes, int n_in,
                              void* d_out, int out_size)
{
    const float2* pos  = (const float2*)d_in[0];
    const float4* feat = (const float4*)d_in[1];
    float* out = (float*)d_out;
    const int n = in_sizes[0] / 2;

    void* counts_ptr = nullptr;
    cudaGetSymbolAddress(&counts_ptr, g_counts);

    cudaMemsetAsync(out, 0, (size_t)out_size * sizeof(float));
    cudaMemsetAsync(counts_ptr, 0, sizeof(int) * NCELLS);

    bin_kernel<<<(n + 255) / 256, 256>>>(pos, feat, out, n);
    cell_kernel<<<NCELLS, 128>>>(feat, out);
}